// round 15
// baseline (speedup 1.0000x reference)
#include <cuda_runtime.h>
#include <cuda_fp16.h>
#include <cuda_bf16.h>
#include <mma.h>

using namespace nvcuda;

// ---------------------------------------------------------------------------
// PhysicsConvolution: X0 = notes@w ; X1 = segment_sum(ew * X0[dst], src) ;
// out = concat(relu(X1 + b), X0[garment:])
//
// R15 = R13 (121.5us; tcgen05 port failed: harness lowers via compute_103
// PTX, no sm_103a-gated instructions available) + ONE change: CSR build
// vectorized (hist + scatter process 4 edges/thread via 128-bit loads).
// ---------------------------------------------------------------------------

#define HD   128
#define BM   128
#define PAD  136

#define MAXN 131072
#define MAXE 1700000
#define SCAN_BLK 1024

#define SMEM_BYTES ((HD * PAD + BM * PAD) * 2)   // 69632 B

__device__ uint4  g_X0q[2200000];       // fp16 X0: [N][16] uint4 (8 halves each)
__device__ int2   g_sdw[MAXE];          // CSR payload {dst, w}
__device__ int    g_cnt[MAXN + 1];      // zero at load; scan restores zeros
__device__ int    g_off[MAXN + 2];
__device__ int    g_cur[MAXN + 1];
__device__ unsigned long long g_agg[256]; // lookback flags; scatter resets

// ---------------------------------------------------------------------------
// GEMM: X0 = Ah@Wh, fp16 operands, fp32 accumulate (identical to R13).
// Block: 8 warps, 128x128 tile; warp (wr, wc) covers rows wr*32..+31,
// cols wc*64..+63.  fp32 C epilogue aliases the whole smem.
// ---------------------------------------------------------------------------
__global__ __launch_bounds__(256) void gemm_kernel(
    const float4* __restrict__ A4,
    const float4* __restrict__ W4,
    float4* __restrict__ out4,
    int N, int g)
{
    extern __shared__ char smem[];
    __half* sWh = reinterpret_cast<__half*>(smem);        // HD x PAD
    __half* sAh = sWh + HD * PAD;                         // BM x PAD
    float*  sC  = reinterpret_cast<float*>(smem);         // BM x HD

    const int tid  = threadIdx.x;
    const int row0 = blockIdx.x * BM;

    #pragma unroll
    for (int i = tid; i < HD * 32; i += 256) {
        int row = i >> 5, c4 = (i & 31) * 4;
        float4 wv = W4[i];
        __half hv[4];
        #pragma unroll
        for (int u = 0; u < 4; u++) hv[u] = __float2half_rn((&wv.x)[u]);
        *reinterpret_cast<uint2*>(sWh + row * PAD + c4) =
            *reinterpret_cast<uint2*>(hv);
    }

    #pragma unroll
    for (int i = tid; i < BM * 32; i += 256) {
        int rl = i >> 5, c4 = (i & 31) * 4;
        int r  = row0 + rl;
        float4 a = (r < N) ? A4[(size_t)r * 32 + (i & 31)]
                           : make_float4(0.f, 0.f, 0.f, 0.f);
        __half hv[4];
        #pragma unroll
        for (int u = 0; u < 4; u++) hv[u] = __float2half_rn((&a.x)[u]);
        *reinterpret_cast<uint2*>(sAh + rl * PAD + c4) =
            *reinterpret_cast<uint2*>(hv);
    }
    __syncthreads();

    const int wid = tid >> 5;
    const int wr  = wid >> 1;
    const int wc  = wid & 1;

    wmma::fragment<wmma::accumulator, 16, 16, 16, float> acc[2][4];
    #pragma unroll
    for (int r = 0; r < 2; r++)
        #pragma unroll
        for (int j = 0; j < 4; j++) wmma::fill_fragment(acc[r][j], 0.f);

    #pragma unroll
    for (int k = 0; k < 8; k++) {
        const int k0 = k * 16;
        wmma::fragment<wmma::matrix_a, 16, 16, 16, __half, wmma::row_major> ah[2];
        #pragma unroll
        for (int r = 0; r < 2; r++)
            wmma::load_matrix_sync(ah[r], sAh + (wr * 32 + r * 16) * PAD + k0, PAD);
        #pragma unroll
        for (int j = 0; j < 4; j++) {
            const int col = wc * 64 + j * 16;
            wmma::fragment<wmma::matrix_b, 16, 16, 16, __half, wmma::row_major> bh;
            wmma::load_matrix_sync(bh, sWh + k0 * PAD + col, PAD);
            #pragma unroll
            for (int r = 0; r < 2; r++)
                wmma::mma_sync(acc[r][j], ah[r], bh, acc[r][j]);
        }
    }

    __syncthreads();
    #pragma unroll
    for (int r = 0; r < 2; r++)
        #pragma unroll
        for (int j = 0; j < 4; j++)
            wmma::store_matrix_sync(
                sC + (wr * 32 + r * 16) * HD + wc * 64 + j * 16,
                acc[r][j], HD, wmma::mem_row_major);
    __syncthreads();

    const int tx = tid & 31;
    const int ty = tid >> 5;
    #pragma unroll
    for (int i = 0; i < 16; i++) {
        int rl = ty * 16 + i;
        int r  = row0 + rl;
        if (r < N) {
            float4 v = *reinterpret_cast<float4*>(sC + rl * HD + tx * 4);
            __half2 lo = __float22half2_rn(make_float2(v.x, v.y));
            __half2 hi = __float22half2_rn(make_float2(v.z, v.w));
            uint2 p;
            p.x = *reinterpret_cast<unsigned*>(&lo);
            p.y = *reinterpret_cast<unsigned*>(&hi);
            reinterpret_cast<uint2*>(g_X0q)[(size_t)r * 32 + tx] = p;
            if (r >= g)
                out4[(size_t)(N + r - g) * 32 + tx] = v;
        }
    }
}

// ---------------------------------------------------------------------------
// Histogram: 4 edges/thread via LDG.128.
// ---------------------------------------------------------------------------
__global__ void hist_kernel(const int* __restrict__ esrc, int E) {
    const int E4 = E >> 2;
    const int stride = gridDim.x * blockDim.x;
    for (int i = blockIdx.x * blockDim.x + threadIdx.x; i < E4; i += stride) {
        int4 s = __ldg(reinterpret_cast<const int4*>(esrc) + i);
        atomicAdd(&g_cnt[s.x], 1);
        atomicAdd(&g_cnt[s.y], 1);
        atomicAdd(&g_cnt[s.z], 1);
        atomicAdd(&g_cnt[s.w], 1);
    }
    // remainder
    for (int e = (E4 << 2) + blockIdx.x * blockDim.x + threadIdx.x; e < E;
         e += stride)
        atomicAdd(&g_cnt[esrc[e]], 1);
}

// ---------------------------------------------------------------------------
// Fused exclusive scan (decoupled lookback), identical to R13.
// ---------------------------------------------------------------------------
__global__ __launch_bounds__(256) void scan_kernel(int N, int E) {
    __shared__ int ssum[256];
    __shared__ int s_bpre;
    const int t   = threadIdx.x;
    const int bid = blockIdx.x;
    const int base = bid * SCAN_BLK + t * 4;

    int c0 = 0, c1 = 0, c2 = 0, c3 = 0;
    if (base + 0 < N) { c0 = g_cnt[base + 0]; g_cnt[base + 0] = 0; }
    if (base + 1 < N) { c1 = g_cnt[base + 1]; g_cnt[base + 1] = 0; }
    if (base + 2 < N) { c2 = g_cnt[base + 2]; g_cnt[base + 2] = 0; }
    if (base + 3 < N) { c3 = g_cnt[base + 3]; g_cnt[base + 3] = 0; }
    int tot = c0 + c1 + c2 + c3;

    ssum[t] = tot;
    __syncthreads();
    #pragma unroll
    for (int off = 1; off < 256; off <<= 1) {
        int v = (t >= off) ? ssum[t - off] : 0;
        __syncthreads();
        ssum[t] += v;
        __syncthreads();
    }
    int ex = ssum[t] - tot;

    if (t == 0)
        atomicExch(&g_agg[bid], (1ULL << 32) | (unsigned)ssum[255]);

    if (t < 32) {
        int prefix = 0;
        for (int ws = 0; ws < bid; ws += 32) {
            int j = ws + t;
            unsigned val = 0;
            if (j < bid) {
                unsigned long long v;
                do { v = atomicAdd(&g_agg[j], 0ULL); } while (!(v >> 32));
                val = (unsigned)v;
            }
            #pragma unroll
            for (int o = 16; o; o >>= 1)
                val += __shfl_down_sync(0xffffffffu, val, o);
            if (t == 0) prefix += (int)val;
        }
        if (t == 0) s_bpre = prefix;
    }
    __syncthreads();

    const int boff = s_bpre;
    if (base + 0 < N) { int v = ex + boff;                g_off[base + 0] = v; g_cur[base + 0] = v; }
    if (base + 1 < N) { int v = ex + c0 + boff;           g_off[base + 1] = v; g_cur[base + 1] = v; }
    if (base + 2 < N) { int v = ex + c0 + c1 + boff;      g_off[base + 2] = v; g_cur[base + 2] = v; }
    if (base + 3 < N) { int v = ex + c0 + c1 + c2 + boff; g_off[base + 3] = v; g_cur[base + 3] = v; }
    if (bid == 0 && t == 0) g_off[N] = E;
}

// ---------------------------------------------------------------------------
// Scatter: 4 edges/thread via 128-bit loads; resets g_agg for next call.
// ---------------------------------------------------------------------------
__global__ void scatter_kernel(const int* __restrict__ esrc,
                               const int* __restrict__ edst,
                               const float* __restrict__ ew, int E) {
    if (blockIdx.x == 0 && threadIdx.x < 256)
        g_agg[threadIdx.x] = 0ULL;

    const int E4 = E >> 2;
    const int stride = gridDim.x * blockDim.x;
    for (int i = blockIdx.x * blockDim.x + threadIdx.x; i < E4; i += stride) {
        int4   s = __ldg(reinterpret_cast<const int4*>(esrc) + i);
        int4   d = __ldg(reinterpret_cast<const int4*>(edst) + i);
        float4 w = __ldg(reinterpret_cast<const float4*>(ew) + i);
        int p0 = atomicAdd(&g_cur[s.x], 1);
        int p1 = atomicAdd(&g_cur[s.y], 1);
        int p2 = atomicAdd(&g_cur[s.z], 1);
        int p3 = atomicAdd(&g_cur[s.w], 1);
        g_sdw[p0] = make_int2(d.x, __float_as_int(w.x));
        g_sdw[p1] = make_int2(d.y, __float_as_int(w.y));
        g_sdw[p2] = make_int2(d.z, __float_as_int(w.z));
        g_sdw[p3] = make_int2(d.w, __float_as_int(w.w));
    }
    for (int e = (E4 << 2) + blockIdx.x * blockDim.x + threadIdx.x; e < E;
         e += stride) {
        int s = esrc[e];
        int p = atomicAdd(&g_cur[s], 1);
        g_sdw[p] = make_int2(edst[e], __float_as_int(ew[e]));
    }
}

// ---------------------------------------------------------------------------
// Gather (identical to R13): 2 nodes/warp, half-warp per node, uint4 loads.
// ---------------------------------------------------------------------------
__global__ __launch_bounds__(256) void gather_kernel(
    const float4* __restrict__ b4,
    float4* __restrict__ out4,
    int N)
{
    const int lane = threadIdx.x & 31;
    const int sub  = lane >> 4;
    const int hl   = lane & 15;
    const int wnum = (blockIdx.x * blockDim.x + threadIdx.x) >> 5;
    const int node = wnum * 2 + sub;
    const bool active = node < N;
    const int  vnode  = active ? node : N - 1;

    const int start = g_off[vnode];
    const int cnt   = active ? (g_off[vnode + 1] - start) : 0;

    const int ocnt   = __shfl_xor_sync(0xffffffffu, cnt, 16);
    const int maxcnt = max(cnt, ocnt);

    float acc[8];
    #pragma unroll
    for (int i = 0; i < 8; i++) acc[i] = 0.f;

    for (int it = 0; it < maxcnt; it += 16) {
        const int m  = min(16, cnt - it);
        const int mu = min(16, maxcnt - it);
        int   dv = 0;
        float wv = 0.f;
        if (hl < m) {
            int2 p = g_sdw[start + it + hl];
            dv = p.x;
            wv = __int_as_float(p.y);
        }
        for (int k = 0; k < mu; k++) {
            int   d = __shfl_sync(0xffffffffu, dv, sub * 16 + k);
            float w = __shfl_sync(0xffffffffu, wv, sub * 16 + k);
            if (k < m) {
                uint4 u = g_X0q[(size_t)d * 16 + hl];
                float2 f0 = __half22float2(*reinterpret_cast<__half2*>(&u.x));
                float2 f1 = __half22float2(*reinterpret_cast<__half2*>(&u.y));
                float2 f2 = __half22float2(*reinterpret_cast<__half2*>(&u.z));
                float2 f3 = __half22float2(*reinterpret_cast<__half2*>(&u.w));
                acc[0] += w * f0.x;  acc[1] += w * f0.y;
                acc[2] += w * f1.x;  acc[3] += w * f1.y;
                acc[4] += w * f2.x;  acc[5] += w * f2.y;
                acc[6] += w * f3.x;  acc[7] += w * f3.y;
            }
        }
    }

    if (active) {
        float4 b0 = __ldg(b4 + hl * 2 + 0);
        float4 b1 = __ldg(b4 + hl * 2 + 1);
        float4 v0 = make_float4(fmaxf(acc[0] + b0.x, 0.f),
                                fmaxf(acc[1] + b0.y, 0.f),
                                fmaxf(acc[2] + b0.z, 0.f),
                                fmaxf(acc[3] + b0.w, 0.f));
        float4 v1 = make_float4(fmaxf(acc[4] + b1.x, 0.f),
                                fmaxf(acc[5] + b1.y, 0.f),
                                fmaxf(acc[6] + b1.z, 0.f),
                                fmaxf(acc[7] + b1.w, 0.f));
        out4[(size_t)node * 32 + hl * 2 + 0] = v0;
        out4[(size_t)node * 32 + hl * 2 + 1] = v1;
    }
}

// ---------------------------------------------------------------------------
extern "C" void kernel_launch(void* const* d_in, const int* in_sizes, int n_in,
                              void* d_out, int out_size)
{
    const float* notes = (const float*)d_in[0];
    const float* w     = (const float*)d_in[1];
    const float* b     = (const float*)d_in[2];
    const int*   esrc  = (const int*)  d_in[3];
    const int*   edst  = (const int*)  d_in[4];
    const float* ew    = (const float*)d_in[5];

    const int H = in_sizes[2];
    const int D = in_sizes[1] / H;
    const int N = in_sizes[0] / D;
    const int E = in_sizes[3];
    const int g = 2 * N - out_size / H;

    float4* out4 = (float4*)d_out;
    const int NB = (N + SCAN_BLK - 1) / SCAN_BLK;

    cudaFuncSetAttribute(gemm_kernel,
                         cudaFuncAttributeMaxDynamicSharedMemorySize,
                         SMEM_BYTES);

    hist_kernel<<<592, 256>>>(esrc, E);
    scan_kernel<<<NB, 256>>>(N, E);
    scatter_kernel<<<592, 256>>>(esrc, edst, ew, E);

    gemm_kernel<<<(N + BM - 1) / BM, 256, SMEM_BYTES>>>(
        (const float4*)notes, (const float4*)w, out4, N, g);

    gather_kernel<<<(N + 15) / 16, 256>>>(
        (const float4*)b, out4, N);
}

// round 16
// speedup vs baseline: 1.3376x; 1.3376x over previous
#include <cuda_runtime.h>
#include <cuda_fp16.h>
#include <cuda_bf16.h>
#include <mma.h>

using namespace nvcuda;

// ---------------------------------------------------------------------------
// PhysicsConvolution: X0 = notes@w ; X1 = segment_sum(ew * X0[dst], src) ;
// out = concat(relu(X1 + b), X0[garment:])
//
// R16 = R13 (121.5us champion) + ONLY the load-path hist vectorization
// (LDG.128, 4 edges/thread).  Scatter reverted to scalar (R13 form).
// R15's uniform ~1.34x slowdown incl. byte-identical GEMM => suspected
// DVFS/slow-clock run, not the code; this round re-anchors the baseline.
// ---------------------------------------------------------------------------

#define HD   128
#define BM   128
#define PAD  136

#define MAXN 131072
#define MAXE 1700000
#define SCAN_BLK 1024

#define SMEM_BYTES ((HD * PAD + BM * PAD) * 2)   // 69632 B

__device__ uint4  g_X0q[2200000];       // fp16 X0: [N][16] uint4 (8 halves each)
__device__ int2   g_sdw[MAXE];          // CSR payload {dst, w}
__device__ int    g_cnt[MAXN + 1];      // zero at load; scan restores zeros
__device__ int    g_off[MAXN + 2];
__device__ int    g_cur[MAXN + 1];
__device__ unsigned long long g_agg[256]; // lookback flags; scatter resets

// ---------------------------------------------------------------------------
// GEMM: X0 = Ah@Wh, fp16 operands, fp32 accumulate (identical to R13).
// Block: 8 warps, 128x128 tile; warp (wr, wc) covers rows wr*32..+31,
// cols wc*64..+63.  fp32 C epilogue aliases the whole smem.
// ---------------------------------------------------------------------------
__global__ __launch_bounds__(256) void gemm_kernel(
    const float4* __restrict__ A4,
    const float4* __restrict__ W4,
    float4* __restrict__ out4,
    int N, int g)
{
    extern __shared__ char smem[];
    __half* sWh = reinterpret_cast<__half*>(smem);        // HD x PAD
    __half* sAh = sWh + HD * PAD;                         // BM x PAD
    float*  sC  = reinterpret_cast<float*>(smem);         // BM x HD

    const int tid  = threadIdx.x;
    const int row0 = blockIdx.x * BM;

    #pragma unroll
    for (int i = tid; i < HD * 32; i += 256) {
        int row = i >> 5, c4 = (i & 31) * 4;
        float4 wv = W4[i];
        __half hv[4];
        #pragma unroll
        for (int u = 0; u < 4; u++) hv[u] = __float2half_rn((&wv.x)[u]);
        *reinterpret_cast<uint2*>(sWh + row * PAD + c4) =
            *reinterpret_cast<uint2*>(hv);
    }

    #pragma unroll
    for (int i = tid; i < BM * 32; i += 256) {
        int rl = i >> 5, c4 = (i & 31) * 4;
        int r  = row0 + rl;
        float4 a = (r < N) ? A4[(size_t)r * 32 + (i & 31)]
                           : make_float4(0.f, 0.f, 0.f, 0.f);
        __half hv[4];
        #pragma unroll
        for (int u = 0; u < 4; u++) hv[u] = __float2half_rn((&a.x)[u]);
        *reinterpret_cast<uint2*>(sAh + rl * PAD + c4) =
            *reinterpret_cast<uint2*>(hv);
    }
    __syncthreads();

    const int wid = tid >> 5;
    const int wr  = wid >> 1;
    const int wc  = wid & 1;

    wmma::fragment<wmma::accumulator, 16, 16, 16, float> acc[2][4];
    #pragma unroll
    for (int r = 0; r < 2; r++)
        #pragma unroll
        for (int j = 0; j < 4; j++) wmma::fill_fragment(acc[r][j], 0.f);

    #pragma unroll
    for (int k = 0; k < 8; k++) {
        const int k0 = k * 16;
        wmma::fragment<wmma::matrix_a, 16, 16, 16, __half, wmma::row_major> ah[2];
        #pragma unroll
        for (int r = 0; r < 2; r++)
            wmma::load_matrix_sync(ah[r], sAh + (wr * 32 + r * 16) * PAD + k0, PAD);
        #pragma unroll
        for (int j = 0; j < 4; j++) {
            const int col = wc * 64 + j * 16;
            wmma::fragment<wmma::matrix_b, 16, 16, 16, __half, wmma::row_major> bh;
            wmma::load_matrix_sync(bh, sWh + k0 * PAD + col, PAD);
            #pragma unroll
            for (int r = 0; r < 2; r++)
                wmma::mma_sync(acc[r][j], ah[r], bh, acc[r][j]);
        }
    }

    __syncthreads();
    #pragma unroll
    for (int r = 0; r < 2; r++)
        #pragma unroll
        for (int j = 0; j < 4; j++)
            wmma::store_matrix_sync(
                sC + (wr * 32 + r * 16) * HD + wc * 64 + j * 16,
                acc[r][j], HD, wmma::mem_row_major);
    __syncthreads();

    const int tx = tid & 31;
    const int ty = tid >> 5;
    #pragma unroll
    for (int i = 0; i < 16; i++) {
        int rl = ty * 16 + i;
        int r  = row0 + rl;
        if (r < N) {
            float4 v = *reinterpret_cast<float4*>(sC + rl * HD + tx * 4);
            __half2 lo = __float22half2_rn(make_float2(v.x, v.y));
            __half2 hi = __float22half2_rn(make_float2(v.z, v.w));
            uint2 p;
            p.x = *reinterpret_cast<unsigned*>(&lo);
            p.y = *reinterpret_cast<unsigned*>(&hi);
            reinterpret_cast<uint2*>(g_X0q)[(size_t)r * 32 + tx] = p;
            if (r >= g)
                out4[(size_t)(N + r - g) * 32 + tx] = v;
        }
    }
}

// ---------------------------------------------------------------------------
// Histogram: 4 edges/thread via LDG.128 (load-path-only change vs R13).
// ---------------------------------------------------------------------------
__global__ void hist_kernel(const int* __restrict__ esrc, int E) {
    const int E4 = E >> 2;
    const int stride = gridDim.x * blockDim.x;
    for (int i = blockIdx.x * blockDim.x + threadIdx.x; i < E4; i += stride) {
        int4 s = __ldg(reinterpret_cast<const int4*>(esrc) + i);
        atomicAdd(&g_cnt[s.x], 1);
        atomicAdd(&g_cnt[s.y], 1);
        atomicAdd(&g_cnt[s.z], 1);
        atomicAdd(&g_cnt[s.w], 1);
    }
    for (int e = (E4 << 2) + blockIdx.x * blockDim.x + threadIdx.x; e < E;
         e += stride)
        atomicAdd(&g_cnt[esrc[e]], 1);
}

// ---------------------------------------------------------------------------
// Fused exclusive scan (decoupled lookback), identical to R13.
// ---------------------------------------------------------------------------
__global__ __launch_bounds__(256) void scan_kernel(int N, int E) {
    __shared__ int ssum[256];
    __shared__ int s_bpre;
    const int t   = threadIdx.x;
    const int bid = blockIdx.x;
    const int base = bid * SCAN_BLK + t * 4;

    int c0 = 0, c1 = 0, c2 = 0, c3 = 0;
    if (base + 0 < N) { c0 = g_cnt[base + 0]; g_cnt[base + 0] = 0; }
    if (base + 1 < N) { c1 = g_cnt[base + 1]; g_cnt[base + 1] = 0; }
    if (base + 2 < N) { c2 = g_cnt[base + 2]; g_cnt[base + 2] = 0; }
    if (base + 3 < N) { c3 = g_cnt[base + 3]; g_cnt[base + 3] = 0; }
    int tot = c0 + c1 + c2 + c3;

    ssum[t] = tot;
    __syncthreads();
    #pragma unroll
    for (int off = 1; off < 256; off <<= 1) {
        int v = (t >= off) ? ssum[t - off] : 0;
        __syncthreads();
        ssum[t] += v;
        __syncthreads();
    }
    int ex = ssum[t] - tot;

    if (t == 0)
        atomicExch(&g_agg[bid], (1ULL << 32) | (unsigned)ssum[255]);

    if (t < 32) {
        int prefix = 0;
        for (int ws = 0; ws < bid; ws += 32) {
            int j = ws + t;
            unsigned val = 0;
            if (j < bid) {
                unsigned long long v;
                do { v = atomicAdd(&g_agg[j], 0ULL); } while (!(v >> 32));
                val = (unsigned)v;
            }
            #pragma unroll
            for (int o = 16; o; o >>= 1)
                val += __shfl_down_sync(0xffffffffu, val, o);
            if (t == 0) prefix += (int)val;
        }
        if (t == 0) s_bpre = prefix;
    }
    __syncthreads();

    const int boff = s_bpre;
    if (base + 0 < N) { int v = ex + boff;                g_off[base + 0] = v; g_cur[base + 0] = v; }
    if (base + 1 < N) { int v = ex + c0 + boff;           g_off[base + 1] = v; g_cur[base + 1] = v; }
    if (base + 2 < N) { int v = ex + c0 + c1 + boff;      g_off[base + 2] = v; g_cur[base + 2] = v; }
    if (base + 3 < N) { int v = ex + c0 + c1 + c2 + boff; g_off[base + 3] = v; g_cur[base + 3] = v; }
    if (bid == 0 && t == 0) g_off[N] = E;
}

// ---------------------------------------------------------------------------
// Scatter (scalar, identical to R13); resets g_agg for next call.
// ---------------------------------------------------------------------------
__global__ void scatter_kernel(const int* __restrict__ esrc,
                               const int* __restrict__ edst,
                               const float* __restrict__ ew, int E) {
    if (blockIdx.x == 0 && threadIdx.x < 256)
        g_agg[threadIdx.x] = 0ULL;
    for (int e = blockIdx.x * blockDim.x + threadIdx.x; e < E;
         e += gridDim.x * blockDim.x) {
        int s = esrc[e];
        int p = atomicAdd(&g_cur[s], 1);
        g_sdw[p] = make_int2(edst[e], __float_as_int(ew[e]));
    }
}

// ---------------------------------------------------------------------------
// Gather (identical to R13): 2 nodes/warp, half-warp per node, uint4 loads.
// ---------------------------------------------------------------------------
__global__ __launch_bounds__(256) void gather_kernel(
    const float4* __restrict__ b4,
    float4* __restrict__ out4,
    int N)
{
    const int lane = threadIdx.x & 31;
    const int sub  = lane >> 4;
    const int hl   = lane & 15;
    const int wnum = (blockIdx.x * blockDim.x + threadIdx.x) >> 5;
    const int node = wnum * 2 + sub;
    const bool active = node < N;
    const int  vnode  = active ? node : N - 1;

    const int start = g_off[vnode];
    const int cnt   = active ? (g_off[vnode + 1] - start) : 0;

    const int ocnt   = __shfl_xor_sync(0xffffffffu, cnt, 16);
    const int maxcnt = max(cnt, ocnt);

    float acc[8];
    #pragma unroll
    for (int i = 0; i < 8; i++) acc[i] = 0.f;

    for (int it = 0; it < maxcnt; it += 16) {
        const int m  = min(16, cnt - it);
        const int mu = min(16, maxcnt - it);
        int   dv = 0;
        float wv = 0.f;
        if (hl < m) {
            int2 p = g_sdw[start + it + hl];
            dv = p.x;
            wv = __int_as_float(p.y);
        }
        for (int k = 0; k < mu; k++) {
            int   d = __shfl_sync(0xffffffffu, dv, sub * 16 + k);
            float w = __shfl_sync(0xffffffffu, wv, sub * 16 + k);
            if (k < m) {
                uint4 u = g_X0q[(size_t)d * 16 + hl];
                float2 f0 = __half22float2(*reinterpret_cast<__half2*>(&u.x));
                float2 f1 = __half22float2(*reinterpret_cast<__half2*>(&u.y));
                float2 f2 = __half22float2(*reinterpret_cast<__half2*>(&u.z));
                float2 f3 = __half22float2(*reinterpret_cast<__half2*>(&u.w));
                acc[0] += w * f0.x;  acc[1] += w * f0.y;
                acc[2] += w * f1.x;  acc[3] += w * f1.y;
                acc[4] += w * f2.x;  acc[5] += w * f2.y;
                acc[6] += w * f3.x;  acc[7] += w * f3.y;
            }
        }
    }

    if (active) {
        float4 b0 = __ldg(b4 + hl * 2 + 0);
        float4 b1 = __ldg(b4 + hl * 2 + 1);
        float4 v0 = make_float4(fmaxf(acc[0] + b0.x, 0.f),
                                fmaxf(acc[1] + b0.y, 0.f),
                                fmaxf(acc[2] + b0.z, 0.f),
                                fmaxf(acc[3] + b0.w, 0.f));
        float4 v1 = make_float4(fmaxf(acc[4] + b1.x, 0.f),
                                fmaxf(acc[5] + b1.y, 0.f),
                                fmaxf(acc[6] + b1.z, 0.f),
                                fmaxf(acc[7] + b1.w, 0.f));
        out4[(size_t)node * 32 + hl * 2 + 0] = v0;
        out4[(size_t)node * 32 + hl * 2 + 1] = v1;
    }
}

// ---------------------------------------------------------------------------
extern "C" void kernel_launch(void* const* d_in, const int* in_sizes, int n_in,
                              void* d_out, int out_size)
{
    const float* notes = (const float*)d_in[0];
    const float* w     = (const float*)d_in[1];
    const float* b     = (const float*)d_in[2];
    const int*   esrc  = (const int*)  d_in[3];
    const int*   edst  = (const int*)  d_in[4];
    const float* ew    = (const float*)d_in[5];

    const int H = in_sizes[2];
    const int D = in_sizes[1] / H;
    const int N = in_sizes[0] / D;
    const int E = in_sizes[3];
    const int g = 2 * N - out_size / H;

    float4* out4 = (float4*)d_out;
    const int NB = (N + SCAN_BLK - 1) / SCAN_BLK;

    cudaFuncSetAttribute(gemm_kernel,
                         cudaFuncAttributeMaxDynamicSharedMemorySize,
                         SMEM_BYTES);

    hist_kernel<<<592, 256>>>(esrc, E);
    scan_kernel<<<NB, 256>>>(N, E);
    scatter_kernel<<<592, 256>>>(esrc, edst, ew, E);

    gemm_kernel<<<(N + BM - 1) / BM, 256, SMEM_BYTES>>>(
        (const float4*)notes, (const float4*)w, out4, N, g);

    gather_kernel<<<(N + 15) / 16, 256>>>(
        (const float4*)b, out4, N);
}